// round 15
// baseline (speedup 1.0000x reference)
#include <cuda_runtime.h>
#include <cuda_fp16.h>
#include <stdint.h>
#include <math.h>

// ---------------- problem constants ----------------
#define NS 32768
#define DD 1024
#define HH 4096

// ---------------- GEMM tiling ----------------
#define BM 256
#define BN 128
#define BKH 128                 // halfs of K per stage (8 x k16 mma steps)
#define NSTAGE 2                // double buffer
#define SPLITZ 16
#define ROWW 68                 // words per padded smem row (64 data + 4 pad)
#define ROWB (ROWW * 4)         // 272 bytes
#define ATILE (BM * ROWB)       // 69632 B
#define BTILE (BN * ROWB)       // 34816 B
#define STAGE_BYTES (ATILE + BTILE)        // 104448 B
#define SMEM_BYTES (NSTAGE * STAGE_BYTES)  // 208896 B (< 227KB cap)

// ---------------- scratch (__device__ globals; no allocs) ----------------
__device__ float  g_S[DD * DD];
__device__ float  g_slab[(size_t)SPLITZ * DD * DD];
__device__ __half g_P[DD * DD];
__device__ __half g_attn[(size_t)NS * DD];
__device__ __half g_hid[(size_t)NS * HH];
__device__ __half g_qt[(size_t)DD * NS];
__device__ __half g_kt[(size_t)DD * NS];
__device__ __half g_vt[(size_t)NS * DD];
__device__ __half g_w1q[(size_t)HH * DD];
__device__ __half g_w2q[(size_t)DD * HH];
__device__ __half g_w1k[(size_t)HH * DD];
__device__ __half g_w2k[(size_t)DD * HH];

// ---------------- helpers ----------------
__device__ __forceinline__ uint32_t smem_u32(const void* p) {
    uint32_t a;
    asm("{ .reg .u64 t; cvta.to.shared.u64 t, %1; cvt.u32.u64 %0, t; }" : "=r"(a) : "l"(p));
    return a;
}
__device__ __forceinline__ void cp16(uint32_t dst, const void* src) {
    asm volatile("cp.async.cg.shared.global [%0], [%1], 16;" :: "r"(dst), "l"(src));
}
#define CP_COMMIT() asm volatile("cp.async.commit_group;" ::: "memory")
#define CP_WAIT0()  asm volatile("cp.async.wait_group 0;" ::: "memory")

#define LDSM4(r, a) \
    asm volatile("ldmatrix.sync.aligned.m8n8.x4.shared.b16 {%0,%1,%2,%3}, [%4];" \
        : "=r"((r)[0]), "=r"((r)[1]), "=r"((r)[2]), "=r"((r)[3]) : "r"(a))

__device__ __forceinline__ void mma16816(float* d, const uint32_t* a,
                                         uint32_t b0, uint32_t b1) {
    asm volatile(
        "mma.sync.aligned.m16n8k16.row.col.f32.f16.f16.f32 "
        "{%0,%1,%2,%3}, {%4,%5,%6,%7}, {%8,%9}, {%0,%1,%2,%3};"
        : "+f"(d[0]), "+f"(d[1]), "+f"(d[2]), "+f"(d[3])
        : "r"(a[0]), "r"(a[1]), "r"(a[2]), "r"(a[3]), "r"(b0), "r"(b1));
}

// load NROWS x 128-half (K-major) fp16 panel into padded smem rows (272B stride)
template<int NROWS>
__device__ __forceinline__ void load_panel(const __half* __restrict__ G, int row0,
                                           int ld, int k0, uint32_t sdst, int tid) {
    #pragma unroll
    for (int i = 0; i < NROWS / 16; i++) {          // NROWS*16 segs / 256 thr
        int idx = tid + i * 256;
        int row = idx >> 4;
        int seg = idx & 15;                         // 16 x 16B (8 halfs) per row
        cp16(sdst + (uint32_t)(row * ROWB + seg * 16),
             G + (size_t)(row0 + row) * ld + k0 + seg * 8);
    }
}

// ---------------- fp16 mma.sync GEMM: C = epi(A[M,K] @ B[N,K]^T) ----------------
// EPI: 0 = fp16 store, 1 = fp32 split-K slab store, 2 = bias+relu -> fp16,
//      3 = bias -> fp32
template<int EPI>
__global__ void __launch_bounds__(256, 1)
tc_gemm(const __half* __restrict__ A, int lda,
        const __half* __restrict__ B, int ldb,
        const float* __restrict__ bias, void* __restrict__ Cv,
        int M, int N, int kPer)
{
    extern __shared__ char smem[];
    const uint32_t sbase = smem_u32(smem);
    const int tid = threadIdx.x;
    const int wid = tid >> 5, lane = tid & 31;
    const int g = lane >> 2, tig = lane & 3;
    const int wm = wid & 3, wn = wid >> 2;          // 4(M) x 2(N) warps -> 64x64 each
    const int m0 = blockIdx.y * BM;
    const int n0 = blockIdx.x * BN;
    const int kBeg = blockIdx.z * kPer;
    const int T = kPer / BKH;

    // per-lane ldmatrix byte offsets (relative to stage A / B bases)
    const uint32_t aOff = (uint32_t)((wm * 64 + (lane & 15)) * ROWB
                                     + ((lane >> 4) << 4));
    const uint32_t bOff = (uint32_t)((wn * 64 + ((lane >> 4) & 1) * 8 + (lane & 7)) * ROWB
                                     + (((lane >> 3) & 1) << 4));

    float acc[4][8][4];
    #pragma unroll
    for (int mt = 0; mt < 4; mt++)
        #pragma unroll
        for (int nt = 0; nt < 8; nt++)
            #pragma unroll
            for (int e = 0; e < 4; e++) acc[mt][nt][e] = 0.f;

    // prologue: stage 0
    load_panel<BM>(A, m0, lda, kBeg, sbase, tid);
    load_panel<BN>(B, n0, ldb, kBeg, sbase + ATILE, tid);
    CP_COMMIT();

    for (int t = 0; t < T; t++) {
        const uint32_t sA = sbase + (t & 1) * STAGE_BYTES;
        const uint32_t sB = sA + ATILE;

        CP_WAIT0();          // stage t landed (it is the only outstanding group)
        __syncthreads();     // visibility + all warps done reading buffer (t+1)&1

        // prefetch t+1 into the other buffer; lands during compute of t
        if (t + 1 < T) {
            uint32_t nbuf = sbase + ((t + 1) & 1) * STAGE_BYTES;
            load_panel<BM>(A, m0, lda, kBeg + (t + 1) * BKH, nbuf, tid);
            load_panel<BN>(B, n0, ldb, kBeg + (t + 1) * BKH, nbuf + ATILE, tid);
        }
        CP_COMMIT();

        #pragma unroll
        for (int ks = 0; ks < 8; ks++) {            // 8 x k16 per stage
            const uint32_t kbb = ks * 32;           // 32 bytes per k16
            uint32_t af[4][4], bf[4][4];
            #pragma unroll
            for (int mt = 0; mt < 4; mt++)
                LDSM4(af[mt], sA + aOff + mt * 16 * ROWB + kbb);
            #pragma unroll
            for (int nt2 = 0; nt2 < 4; nt2++)
                LDSM4(bf[nt2], sB + bOff + nt2 * 16 * ROWB + kbb);
            #pragma unroll
            for (int nt2 = 0; nt2 < 4; nt2++)
                #pragma unroll
                for (int h = 0; h < 2; h++) {
                    const int nt = nt2 * 2 + h;
                    #pragma unroll
                    for (int mt = 0; mt < 4; mt++)
                        mma16816(acc[mt][nt], af[mt], bf[nt2][h * 2], bf[nt2][h * 2 + 1]);
                }
        }
    }

    // ---- epilogue (fragment layout validated in R8/R13) ----
    const size_t slab = (EPI == 1) ? (size_t)blockIdx.z * (size_t)M * (size_t)N : 0;
    float*  Cf = (float*)Cv;
    __half* Ch = (__half*)Cv;

    #pragma unroll
    for (int mt = 0; mt < 4; mt++) {
        const int row = m0 + wm * 64 + mt * 16 + g;
        #pragma unroll
        for (int nt = 0; nt < 8; nt++) {
            const int col = n0 + wn * 64 + nt * 8 + tig * 2;
            float c0 = acc[mt][nt][0], c1 = acc[mt][nt][1];
            float c2 = acc[mt][nt][2], c3 = acc[mt][nt][3];
            if (EPI == 2 || EPI == 3) {
                float2 bv = *(const float2*)&bias[col];
                c0 += bv.x; c1 += bv.y; c2 += bv.x; c3 += bv.y;
            }
            if (EPI == 2) {
                c0 = fmaxf(c0, 0.f); c1 = fmaxf(c1, 0.f);
                c2 = fmaxf(c2, 0.f); c3 = fmaxf(c3, 0.f);
            }
            if (EPI == 0 || EPI == 2) {
                *(__half2*)&Ch[(size_t)row * N + col]       = __floats2half2_rn(c0, c1);
                *(__half2*)&Ch[(size_t)(row + 8) * N + col] = __floats2half2_rn(c2, c3);
            } else {
                *(float2*)&Cf[slab + (size_t)row * N + col]       = make_float2(c0, c1);
                *(float2*)&Cf[slab + (size_t)(row + 8) * N + col] = make_float2(c2, c3);
            }
        }
    }
}

// ---------------- aux kernels ----------------
// vectorized transpose fp32 [R,C] -> fp16 [C,R], 64x64 tiles, 256 threads
__global__ void transpose_h(const float* __restrict__ in, __half* __restrict__ out,
                            int R, int C)
{
    __shared__ float ts[64][65];
    const int c0 = blockIdx.x * 64, r0 = blockIdx.y * 64;
    const int tid = threadIdx.x;

    #pragma unroll
    for (int i = 0; i < 4; i++) {
        int idx = tid + i * 256;
        int row = idx >> 4;
        int q   = idx & 15;
        float4 v = *(const float4*)&in[(size_t)(r0 + row) * C + c0 + q * 4];
        ts[row][q * 4 + 0] = v.x;
        ts[row][q * 4 + 1] = v.y;
        ts[row][q * 4 + 2] = v.z;
        ts[row][q * 4 + 3] = v.w;
    }
    __syncthreads();

    #pragma unroll
    for (int i = 0; i < 8; i++) {
        int idx = tid + i * 256;
        int c  = idx >> 5;
        int rg = idx & 31;
        __half2 h = __floats2half2_rn(ts[rg * 2][c], ts[rg * 2 + 1][c]);
        *(__half2*)&out[(size_t)(c0 + c) * R + r0 + rg * 2] = h;
    }
}

// fp32 -> fp16 copy
__global__ void copy_h(const float4* __restrict__ in, __half2* __restrict__ out,
                       size_t n4)
{
    size_t i = (size_t)blockIdx.x * blockDim.x + threadIdx.x;
    if (i < n4) {
        float4 v = in[i];
        out[i * 2]     = __floats2half2_rn(v.x, v.y);
        out[i * 2 + 1] = __floats2half2_rn(v.z, v.w);
    }
}

__global__ void reduceZ_kernel(const float* __restrict__ part, float* __restrict__ S)
{
    int i = blockIdx.x * blockDim.x + threadIdx.x;
    float s = 0.f;
    #pragma unroll
    for (int z = 0; z < SPLITZ; z++) s += part[(size_t)z * (DD * DD) + i];
    S[i] = s;
}

// double-exp row softmax; fp16 output (feeds attn GEMM as B)
__global__ void softmax_kernel(const float* __restrict__ S, __half* __restrict__ P)
{
    const int row = blockIdx.x;
    const int tid = threadIdx.x;
    __shared__ float red[256];

    float l[4];
    float mx = -1e30f;
    #pragma unroll
    for (int r = 0; r < 4; r++) {
        int col = tid + r * 256;
        float s = S[(size_t)row * DD + col];
        float scale = (col == row) ? (1.0f - 1.0f / 32.0f) : 1.0f;  // sqrt(1024)=32
        l[r] = expf(s * scale);
        mx = fmaxf(mx, l[r]);
    }
    red[tid] = mx;
    __syncthreads();
    for (int s = 128; s > 0; s >>= 1) {
        if (tid < s) red[tid] = fmaxf(red[tid], red[tid + s]);
        __syncthreads();
    }
    mx = red[0];
    __syncthreads();

    float e[4], sum = 0.f;
    #pragma unroll
    for (int r = 0; r < 4; r++) { e[r] = expf(l[r] - mx); sum += e[r]; }
    red[tid] = sum;
    __syncthreads();
    for (int s = 128; s > 0; s >>= 1) {
        if (tid < s) red[tid] += red[tid + s];
        __syncthreads();
    }
    float inv = 1.0f / red[0];
    #pragma unroll
    for (int r = 0; r < 4; r++) {
        int col = tid + r * 256;
        P[(size_t)row * DD + col] = __float2half_rn(e[r] * inv);
    }
}

// ---------------- launch ----------------
extern "C" void kernel_launch(void* const* d_in, const int* in_sizes, int n_in,
                              void* d_out, int out_size)
{
    const float* q   = (const float*)d_in[0];
    const float* k   = (const float*)d_in[1];
    const float* v   = (const float*)d_in[2];
    const float* wq1 = (const float*)d_in[3];
    const float* bq1 = (const float*)d_in[4];
    const float* wq2 = (const float*)d_in[5];
    const float* bq2 = (const float*)d_in[6];
    const float* wk1 = (const float*)d_in[7];
    const float* bk1 = (const float*)d_in[8];
    const float* wk2 = (const float*)d_in[9];
    const float* bk2 = (const float*)d_in[10];
    float* out = (float*)d_out;

    float *S, *slab;
    __half *P, *attn, *hid, *qt, *kt, *vt, *w1q, *w2q, *w1k, *w2k;
    cudaGetSymbolAddress((void**)&S,    g_S);
    cudaGetSymbolAddress((void**)&slab, g_slab);
    cudaGetSymbolAddress((void**)&P,    g_P);
    cudaGetSymbolAddress((void**)&attn, g_attn);
    cudaGetSymbolAddress((void**)&hid,  g_hid);
    cudaGetSymbolAddress((void**)&qt,   g_qt);
    cudaGetSymbolAddress((void**)&kt,   g_kt);
    cudaGetSymbolAddress((void**)&vt,   g_vt);
    cudaGetSymbolAddress((void**)&w1q,  g_w1q);
    cudaGetSymbolAddress((void**)&w2q,  g_w2q);
    cudaGetSymbolAddress((void**)&w1k,  g_w1k);
    cudaGetSymbolAddress((void**)&w2k,  g_w2k);

    cudaFuncSetAttribute(tc_gemm<0>, cudaFuncAttributeMaxDynamicSharedMemorySize, SMEM_BYTES);
    cudaFuncSetAttribute(tc_gemm<1>, cudaFuncAttributeMaxDynamicSharedMemorySize, SMEM_BYTES);
    cudaFuncSetAttribute(tc_gemm<2>, cudaFuncAttributeMaxDynamicSharedMemorySize, SMEM_BYTES);
    cudaFuncSetAttribute(tc_gemm<3>, cudaFuncAttributeMaxDynamicSharedMemorySize, SMEM_BYTES);

    // 0) operand prep (R13 dataflow; faster 64x64 transpose kept)
    transpose_h<<<dim3(DD / 64, NS / 64), 256>>>(q, qt, NS, DD);
    transpose_h<<<dim3(DD / 64, NS / 64), 256>>>(k, kt, NS, DD);
    copy_h<<<(int)((size_t)NS * DD / 4 / 256), 256>>>(
        (const float4*)v, (__half2*)vt, (size_t)NS * DD / 4);
    transpose_h<<<dim3(HH / 64, DD / 64), 256>>>(wq1, w1q, DD, HH);
    transpose_h<<<dim3(DD / 64, HH / 64), 256>>>(wq2, w2q, HH, DD);
    transpose_h<<<dim3(HH / 64, DD / 64), 256>>>(wk1, w1k, DD, HH);
    transpose_h<<<dim3(DD / 64, HH / 64), 256>>>(wk2, w2k, HH, DD);

    // 1) S = Q^T K : split-K=16 fp32 slabs + deterministic reduce
    tc_gemm<1><<<dim3(DD / BN, DD / BM, SPLITZ), 256, SMEM_BYTES>>>(
        qt, NS, kt, NS, nullptr, slab, DD, DD, NS / SPLITZ);
    reduceZ_kernel<<<(DD * DD) / 256, 256>>>(slab, S);

    // 2) softmax -> P (fp16)
    softmax_kernel<<<DD, 256>>>(S, P);

    // 3) attn = V @ P^T -> fp16
    tc_gemm<0><<<dim3(DD / BN, NS / BM, 1), 256, SMEM_BYTES>>>(
        vt, DD, P, DD, nullptr, attn, NS, DD, DD);

    // 4) query branch
    tc_gemm<2><<<dim3(HH / BN, NS / BM, 1), 256, SMEM_BYTES>>>(
        attn, DD, w1q, DD, bq1, hid, NS, HH, DD);
    tc_gemm<3><<<dim3(DD / BN, NS / BM, 1), 256, SMEM_BYTES>>>(
        hid, HH, w2q, HH, bq2, out, NS, DD, HH);

    // 5) key branch
    tc_gemm<2><<<dim3(HH / BN, NS / BM, 1), 256, SMEM_BYTES>>>(
        attn, DD, w1k, DD, bk1, hid, NS, HH, DD);
    tc_gemm<3><<<dim3(DD / BN, NS / BM, 1), 256, SMEM_BYTES>>>(
        hid, HH, w2k, HH, bk2, out + (size_t)NS * DD, NS, DD, HH);
}

// round 16
// speedup vs baseline: 1.1503x; 1.1503x over previous
#include <cuda_runtime.h>
#include <cuda_fp16.h>
#include <stdint.h>
#include <math.h>

// ---------------- problem constants ----------------
#define NS 32768
#define DD 1024
#define HH 4096

// ---------------- GEMM tiling ----------------
#define BM 128
#define BN 128
#define BKH 64                  // halfs of K per stage (4 x k16 mma steps)
#define NSTAGE 3
#define SPLITZ 16
#define ROWW 36                 // words per padded smem row (32 data + 4 pad)
#define ROWB (ROWW * 4)         // 144 bytes
#define ATILE (BM * ROWB)       // 18432 B
#define BTILE (BN * ROWB)       // 18432 B
#define STAGE_BYTES (ATILE + BTILE)        // 36864 B
#define SMEM_BYTES (NSTAGE * STAGE_BYTES)  // 110592 B -> 2 CTAs/SM

// ---------------- scratch (__device__ globals; no allocs) ----------------
__device__ float  g_S[DD * DD];
__device__ float  g_slab[(size_t)SPLITZ * DD * DD];
__device__ __half g_P[DD * DD];
__device__ __half g_attn[(size_t)NS * DD];
__device__ __half g_hid[(size_t)NS * HH];
__device__ __half g_qt[(size_t)DD * NS];
__device__ __half g_kt[(size_t)DD * NS];
__device__ __half g_vt[(size_t)NS * DD];
__device__ __half g_w1q[(size_t)HH * DD];
__device__ __half g_w2q[(size_t)DD * HH];
__device__ __half g_w1k[(size_t)HH * DD];
__device__ __half g_w2k[(size_t)DD * HH];

// ---------------- helpers ----------------
__device__ __forceinline__ uint32_t smem_u32(const void* p) {
    uint32_t a;
    asm("{ .reg .u64 t; cvta.to.shared.u64 t, %1; cvt.u32.u64 %0, t; }" : "=r"(a) : "l"(p));
    return a;
}
__device__ __forceinline__ void cp16(uint32_t dst, const void* src) {
    asm volatile("cp.async.cg.shared.global [%0], [%1], 16;" :: "r"(dst), "l"(src));
}
#define CP_COMMIT() asm volatile("cp.async.commit_group;" ::: "memory")
#define CP_WAIT1()  asm volatile("cp.async.wait_group 1;" ::: "memory")

#define LDSM4(r, a) \
    asm volatile("ldmatrix.sync.aligned.m8n8.x4.shared.b16 {%0,%1,%2,%3}, [%4];" \
        : "=r"((r)[0]), "=r"((r)[1]), "=r"((r)[2]), "=r"((r)[3]) : "r"(a))

__device__ __forceinline__ void mma16816(float* d, const uint32_t* a,
                                         uint32_t b0, uint32_t b1) {
    asm volatile(
        "mma.sync.aligned.m16n8k16.row.col.f32.f16.f16.f32 "
        "{%0,%1,%2,%3}, {%4,%5,%6,%7}, {%8,%9}, {%0,%1,%2,%3};"
        : "+f"(d[0]), "+f"(d[1]), "+f"(d[2]), "+f"(d[3])
        : "r"(a[0]), "r"(a[1]), "r"(a[2]), "r"(a[3]), "r"(b0), "r"(b1));
}

// load NROWS x 64-half (K-major) fp16 panel into padded smem rows (144B stride)
template<int NROWS>
__device__ __forceinline__ void load_panel(const __half* __restrict__ G, int row0,
                                           int ld, int k0, uint32_t sdst, int tid) {
    #pragma unroll
    for (int i = 0; i < NROWS / 32; i++) {          // NROWS*8 segs / 256 thr
        int idx = tid + i * 256;
        int row = idx >> 3;
        int seg = idx & 7;                          // 8 x 16B (8 halfs) per row
        cp16(sdst + (uint32_t)(row * ROWB + seg * 16),
             G + (size_t)(row0 + row) * ld + k0 + seg * 8);
    }
}

// ---------------- fp16 mma.sync GEMM: C = epi(A[M,K] @ B[N,K]^T) ----------------
// EPI: 0 = fp16 store, 1 = fp32 split-K slab store, 2 = bias+relu -> fp16,
//      3 = bias -> fp32
template<int EPI>
__global__ void __launch_bounds__(256, 2)
tc_gemm(const __half* __restrict__ A, int lda,
        const __half* __restrict__ B, int ldb,
        const float* __restrict__ bias, void* __restrict__ Cv,
        int M, int N, int kPer)
{
    extern __shared__ char smem[];
    const uint32_t sbase = smem_u32(smem);
    const int tid = threadIdx.x;
    const int wid = tid >> 5, lane = tid & 31;
    const int g = lane >> 2, tig = lane & 3;
    const int wm = wid & 3, wn = wid >> 2;          // 4(M) x 2(N) warps -> 32x64 each
    const int m0 = blockIdx.y * BM;
    const int n0 = blockIdx.x * BN;
    const int kBeg = blockIdx.z * kPer;
    const int T = kPer / BKH;

    // per-lane ldmatrix byte offsets (relative to stage A / B bases)
    const uint32_t aOff = (uint32_t)((wm * 32 + (lane & 15)) * ROWB
                                     + ((lane >> 4) << 4));
    const uint32_t bOff = (uint32_t)((wn * 64 + ((lane >> 4) & 1) * 8 + (lane & 7)) * ROWB
                                     + (((lane >> 3) & 1) << 4));

    float acc[2][8][4];
    #pragma unroll
    for (int mt = 0; mt < 2; mt++)
        #pragma unroll
        for (int nt = 0; nt < 8; nt++)
            #pragma unroll
            for (int e = 0; e < 4; e++) acc[mt][nt][e] = 0.f;

    // prologue: stages 0,1
    #pragma unroll
    for (int p = 0; p < NSTAGE - 1; p++) {
        uint32_t buf = sbase + p * STAGE_BYTES;
        load_panel<BM>(A, m0, lda, kBeg + p * BKH, buf, tid);
        load_panel<BN>(B, n0, ldb, kBeg + p * BKH, buf + ATILE, tid);
        CP_COMMIT();
    }

    for (int t = 0; t < T; t++) {
        const int s = t % NSTAGE;
        const uint32_t sA = sbase + s * STAGE_BYTES;
        const uint32_t sB = sA + ATILE;

        CP_WAIT1();          // stage t landed (only stage t+1 in flight)
        __syncthreads();     // visibility + all warps done reading stage (t-1)%3

        #pragma unroll
        for (int ks = 0; ks < 4; ks++) {            // 4 x k16 per stage
            const uint32_t kbb = ks * 32;           // 32 bytes per k16
            uint32_t af[2][4], bf[4][4];
            #pragma unroll
            for (int mt = 0; mt < 2; mt++)
                LDSM4(af[mt], sA + aOff + mt * 16 * ROWB + kbb);
            #pragma unroll
            for (int nt2 = 0; nt2 < 4; nt2++)
                LDSM4(bf[nt2], sB + bOff + nt2 * 16 * ROWB + kbb);
            #pragma unroll
            for (int nt2 = 0; nt2 < 4; nt2++)
                #pragma unroll
                for (int h = 0; h < 2; h++) {
                    const int nt = nt2 * 2 + h;
                    #pragma unroll
                    for (int mt = 0; mt < 2; mt++)
                        mma16816(acc[mt][nt], af[mt], bf[nt2][h * 2], bf[nt2][h * 2 + 1]);
                }
        }

        const int tn = t + NSTAGE - 1;
        if (tn < T) {
            uint32_t nbuf = sbase + (tn % NSTAGE) * STAGE_BYTES;
            load_panel<BM>(A, m0, lda, kBeg + tn * BKH, nbuf, tid);
            load_panel<BN>(B, n0, ldb, kBeg + tn * BKH, nbuf + ATILE, tid);
        }
        CP_COMMIT();         // exactly one group per iter keeps accounting exact
    }

    // ---- epilogue (fragment layout validated in R8/R13) ----
    const size_t slab = (EPI == 1) ? (size_t)blockIdx.z * (size_t)M * (size_t)N : 0;
    float*  Cf = (float*)Cv;
    __half* Ch = (__half*)Cv;

    #pragma unroll
    for (int mt = 0; mt < 2; mt++) {
        const int row = m0 + wm * 32 + mt * 16 + g;
        #pragma unroll
        for (int nt = 0; nt < 8; nt++) {
            const int col = n0 + wn * 64 + nt * 8 + tig * 2;
            float c0 = acc[mt][nt][0], c1 = acc[mt][nt][1];
            float c2 = acc[mt][nt][2], c3 = acc[mt][nt][3];
            if (EPI == 2 || EPI == 3) {
                float2 bv = *(const float2*)&bias[col];
                c0 += bv.x; c1 += bv.y; c2 += bv.x; c3 += bv.y;
            }
            if (EPI == 2) {
                c0 = fmaxf(c0, 0.f); c1 = fmaxf(c1, 0.f);
                c2 = fmaxf(c2, 0.f); c3 = fmaxf(c3, 0.f);
            }
            if (EPI == 0 || EPI == 2) {
                *(__half2*)&Ch[(size_t)row * N + col]       = __floats2half2_rn(c0, c1);
                *(__half2*)&Ch[(size_t)(row + 8) * N + col] = __floats2half2_rn(c2, c3);
            } else {
                *(float2*)&Cf[slab + (size_t)row * N + col]       = make_float2(c0, c1);
                *(float2*)&Cf[slab + (size_t)(row + 8) * N + col] = make_float2(c2, c3);
            }
        }
    }
}

// ---------------- aux kernels ----------------
// vectorized transpose fp32 [R,C] -> fp16 [C,R], 64x64 tiles, 256 threads
__global__ void transpose_h(const float* __restrict__ in, __half* __restrict__ out,
                            int R, int C)
{
    __shared__ float ts[64][65];
    const int c0 = blockIdx.x * 64, r0 = blockIdx.y * 64;
    const int tid = threadIdx.x;

    #pragma unroll
    for (int i = 0; i < 4; i++) {
        int idx = tid + i * 256;
        int row = idx >> 4;
        int q   = idx & 15;
        float4 v = *(const float4*)&in[(size_t)(r0 + row) * C + c0 + q * 4];
        ts[row][q * 4 + 0] = v.x;
        ts[row][q * 4 + 1] = v.y;
        ts[row][q * 4 + 2] = v.z;
        ts[row][q * 4 + 3] = v.w;
    }
    __syncthreads();

    #pragma unroll
    for (int i = 0; i < 8; i++) {
        int idx = tid + i * 256;
        int c  = idx >> 5;
        int rg = idx & 31;
        __half2 h = __floats2half2_rn(ts[rg * 2][c], ts[rg * 2 + 1][c]);
        *(__half2*)&out[(size_t)(c0 + c) * R + r0 + rg * 2] = h;
    }
}

// fp32 -> fp16 copy
__global__ void copy_h(const float4* __restrict__ in, __half2* __restrict__ out,
                       size_t n4)
{
    size_t i = (size_t)blockIdx.x * blockDim.x + threadIdx.x;
    if (i < n4) {
        float4 v = in[i];
        out[i * 2]     = __floats2half2_rn(v.x, v.y);
        out[i * 2 + 1] = __floats2half2_rn(v.z, v.w);
    }
}

__global__ void reduceZ_kernel(const float* __restrict__ part, float* __restrict__ S)
{
    int i = blockIdx.x * blockDim.x + threadIdx.x;
    float s = 0.f;
    #pragma unroll
    for (int z = 0; z < SPLITZ; z++) s += part[(size_t)z * (DD * DD) + i];
    S[i] = s;
}

// double-exp row softmax; fp16 output (feeds attn GEMM as B)
__global__ void softmax_kernel(const float* __restrict__ S, __half* __restrict__ P)
{
    const int row = blockIdx.x;
    const int tid = threadIdx.x;
    __shared__ float red[256];

    float l[4];
    float mx = -1e30f;
    #pragma unroll
    for (int r = 0; r < 4; r++) {
        int col = tid + r * 256;
        float s = S[(size_t)row * DD + col];
        float scale = (col == row) ? (1.0f - 1.0f / 32.0f) : 1.0f;  // sqrt(1024)=32
        l[r] = expf(s * scale);
        mx = fmaxf(mx, l[r]);
    }
    red[tid] = mx;
    __syncthreads();
    for (int s = 128; s > 0; s >>= 1) {
        if (tid < s) red[tid] = fmaxf(red[tid], red[tid + s]);
        __syncthreads();
    }
    mx = red[0];
    __syncthreads();

    float e[4], sum = 0.f;
    #pragma unroll
    for (int r = 0; r < 4; r++) { e[r] = expf(l[r] - mx); sum += e[r]; }
    red[tid] = sum;
    __syncthreads();
    for (int s = 128; s > 0; s >>= 1) {
        if (tid < s) red[tid] += red[tid + s];
        __syncthreads();
    }
    float inv = 1.0f / red[0];
    #pragma unroll
    for (int r = 0; r < 4; r++) {
        int col = tid + r * 256;
        P[(size_t)row * DD + col] = __float2half_rn(e[r] * inv);
    }
}

// ---------------- launch ----------------
extern "C" void kernel_launch(void* const* d_in, const int* in_sizes, int n_in,
                              void* d_out, int out_size)
{
    const float* q   = (const float*)d_in[0];
    const float* k   = (const float*)d_in[1];
    const float* v   = (const float*)d_in[2];
    const float* wq1 = (const float*)d_in[3];
    const float* bq1 = (const float*)d_in[4];
    const float* wq2 = (const float*)d_in[5];
    const float* bq2 = (const float*)d_in[6];
    const float* wk1 = (const float*)d_in[7];
    const float* bk1 = (const float*)d_in[8];
    const float* wk2 = (const float*)d_in[9];
    const float* bk2 = (const float*)d_in[10];
    float* out = (float*)d_out;

    float *S, *slab;
    __half *P, *attn, *hid, *qt, *kt, *vt, *w1q, *w2q, *w1k, *w2k;
    cudaGetSymbolAddress((void**)&S,    g_S);
    cudaGetSymbolAddress((void**)&slab, g_slab);
    cudaGetSymbolAddress((void**)&P,    g_P);
    cudaGetSymbolAddress((void**)&attn, g_attn);
    cudaGetSymbolAddress((void**)&hid,  g_hid);
    cudaGetSymbolAddress((void**)&qt,   g_qt);
    cudaGetSymbolAddress((void**)&kt,   g_kt);
    cudaGetSymbolAddress((void**)&vt,   g_vt);
    cudaGetSymbolAddress((void**)&w1q,  g_w1q);
    cudaGetSymbolAddress((void**)&w2q,  g_w2q);
    cudaGetSymbolAddress((void**)&w1k,  g_w1k);
    cudaGetSymbolAddress((void**)&w2k,  g_w2k);

    cudaFuncSetAttribute(tc_gemm<0>, cudaFuncAttributeMaxDynamicSharedMemorySize, SMEM_BYTES);
    cudaFuncSetAttribute(tc_gemm<1>, cudaFuncAttributeMaxDynamicSharedMemorySize, SMEM_BYTES);
    cudaFuncSetAttribute(tc_gemm<2>, cudaFuncAttributeMaxDynamicSharedMemorySize, SMEM_BYTES);
    cudaFuncSetAttribute(tc_gemm<3>, cudaFuncAttributeMaxDynamicSharedMemorySize, SMEM_BYTES);

    // 0) operand prep
    transpose_h<<<dim3(DD / 64, NS / 64), 256>>>(q, qt, NS, DD);
    transpose_h<<<dim3(DD / 64, NS / 64), 256>>>(k, kt, NS, DD);
    copy_h<<<(int)((size_t)NS * DD / 4 / 256), 256>>>(
        (const float4*)v, (__half2*)vt, (size_t)NS * DD / 4);
    transpose_h<<<dim3(HH / 64, DD / 64), 256>>>(wq1, w1q, DD, HH);
    transpose_h<<<dim3(DD / 64, HH / 64), 256>>>(wq2, w2q, HH, DD);
    transpose_h<<<dim3(HH / 64, DD / 64), 256>>>(wk1, w1k, DD, HH);
    transpose_h<<<dim3(DD / 64, HH / 64), 256>>>(wk2, w2k, HH, DD);

    // 1) S = Q^T K : split-K=16 fp32 slabs + deterministic reduce
    tc_gemm<1><<<dim3(DD / BN, DD / BM, SPLITZ), 256, SMEM_BYTES>>>(
        qt, NS, kt, NS, nullptr, slab, DD, DD, NS / SPLITZ);
    reduceZ_kernel<<<(DD * DD) / 256, 256>>>(slab, S);

    // 2) softmax -> P (fp16)
    softmax_kernel<<<DD, 256>>>(S, P);

    // 3) attn = V @ P^T -> fp16
    tc_gemm<0><<<dim3(DD / BN, NS / BM, 1), 256, SMEM_BYTES>>>(
        vt, DD, P, DD, nullptr, attn, NS, DD, DD);

    // 4) query branch
    tc_gemm<2><<<dim3(HH / BN, NS / BM, 1), 256, SMEM_BYTES>>>(
        attn, DD, w1q, DD, bq1, hid, NS, HH, DD);
    tc_gemm<3><<<dim3(DD / BN, NS / BM, 1), 256, SMEM_BYTES>>>(
        hid, HH, w2q, HH, bq2, out, NS, DD, HH);

    // 5) key branch
    tc_gemm<2><<<dim3(HH / BN, NS / BM, 1), 256, SMEM_BYTES>>>(
        attn, DD, w1k, DD, bk1, hid, NS, HH, DD);
    tc_gemm<3><<<dim3(DD / BN, NS / BM, 1), 256, SMEM_BYTES>>>(
        hid, HH, w2k, HH, bk2, out + (size_t)NS * DD, NS, DD, HH);
}